// round 17
// baseline (speedup 1.0000x reference)
#include <cuda_runtime.h>
#include <cuda_bf16.h>
#include <stdint.h>

#define NN 100000
#define NE 1600000
#define HID 128

// ---------------- device scratch ----------------
__device__ int   g_src[NE];
__device__ int   g_dst[NE];
__device__ float g_dis[NN];
__device__ int   g_cursor[NN];
__device__ int   g_rowptr[NN + 1];
__device__ int   g_partials[256];
__device__ __align__(16) int2 g_edge[NE];        // packed (src, coef-bits)
__device__ float g_a1[NN];
__device__ __align__(16) float g_h1[(size_t)NN * HID];
__device__ __align__(16) float g_agg[(size_t)NN * HID];
// pre-split transposed weights (bf16 hi/lo)
__device__ __align__(16) unsigned short g_W2T_hi[256 * 128];
__device__ __align__(16) unsigned short g_W2T_lo[256 * 128];
__device__ __align__(16) unsigned short g_Wl1T_hi[128 * 256];
__device__ __align__(16) unsigned short g_Wl1T_lo[128 * 256];

// ================= front-end (unchanged from 419us baseline) ==================
__global__ void k_init(void) {
    int i = blockIdx.x * blockDim.x + threadIdx.x;
    if (i < NN) { g_dis[i] = 1.0f; g_cursor[i] = 0; g_a1[i] = 0.f; }
}

__global__ void k_conv_deg(const void* ei, const float* __restrict__ w) {
    __shared__ int sflag;
    int t = threadIdx.x;
    if (t < 32) {
        const long long* p = (const long long*)ei;
        long long v = p[(long long)t * (NE / 32)];
        bool ok = (v >= 0 && v < NN);
        unsigned m = __ballot_sync(0xFFFFFFFFu, ok);
        if (t == 0) sflag = (m == 0xFFFFFFFFu) ? 1 : 0;
    }
    __syncthreads();
    int e = blockIdx.x * blockDim.x + t;
    if (e >= NE) return;
    int s, d;
    if (sflag) {
        const long long* p = (const long long*)ei;
        s = (int)p[e]; d = (int)p[e + NE];
    } else {
        const int* p = (const int*)ei;
        s = p[e]; d = p[e + NE];
    }
    g_src[e] = s; g_dst[e] = d;
    atomicAdd(&g_dis[d], w[e]);
    atomicAdd(&g_cursor[d], 1);
}

#define SCHUNK 512
#define NCHUNK ((NN + SCHUNK - 1) / SCHUNK)
__global__ void k_scan1(void) {
    __shared__ int sh[SCHUNK];
    int t = threadIdx.x;
    int idx = blockIdx.x * SCHUNK + t;
    int v = (idx < NN) ? g_cursor[idx] : 0;
    sh[t] = v;
    __syncthreads();
    for (int off = 1; off < SCHUNK; off <<= 1) {
        int u = (t >= off) ? sh[t - off] : 0;
        __syncthreads();
        sh[t] += u;
        __syncthreads();
    }
    if (idx < NN) g_rowptr[idx] = sh[t] - v;
    if (t == SCHUNK - 1) g_partials[blockIdx.x] = sh[SCHUNK - 1];
}
__global__ void k_scan2(void) {
    int acc = 0;
    for (int b = 0; b < NCHUNK; b++) { int v = g_partials[b]; g_partials[b] = acc; acc += v; }
}
__global__ void k_scan3(void) {
    int i = blockIdx.x * blockDim.x + threadIdx.x;
    if (i < NN) {
        int r = g_rowptr[i] + g_partials[i >> 9];
        g_rowptr[i] = r; g_cursor[i] = r;
        g_dis[i] = rsqrtf(g_dis[i]);
    }
    if (i == 0) g_rowptr[NN] = NE;
}

__global__ void k_fill(const float* __restrict__ w, const float* __restrict__ x) {
    int e = blockIdx.x * blockDim.x + threadIdx.x;
    if (e >= NE) return;
    int d = g_dst[e], s = g_src[e];
    float c = g_dis[s] * w[e] * g_dis[d];
    int pos = atomicAdd(&g_cursor[d], 1);
    g_edge[pos] = make_int2(s, __float_as_int(c));
    atomicAdd(&g_a1[d], c * __ldg(&x[s]));
}

__global__ void k_expand(const float* __restrict__ x,
                         const float* __restrict__ W1,
                         const float* __restrict__ b1) {
    int gt = blockIdx.x * blockDim.x + threadIdx.x;
    int node = gt >> 5, lane = gt & 31;
    if (node >= NN) return;
    float dd = g_dis[node];
    float a  = g_a1[node] + dd * dd * x[node];
    float4* dst = (float4*)(g_h1 + (size_t)node * HID);
    const float4* W4 = (const float4*)W1;
    const float4* b4 = (const float4*)b1;
    float4 wv = W4[lane], bv = b4[lane];
    float4 o;
    o.x = fmaxf(fmaf(a, wv.x, bv.x), 0.f);
    o.y = fmaxf(fmaf(a, wv.y, bv.y), 0.f);
    o.z = fmaxf(fmaf(a, wv.z, bv.z), 0.f);
    o.w = fmaxf(fmaf(a, wv.w, bv.w), 0.f);
    dst[lane] = o;
}

__global__ __launch_bounds__(HID) void k_agg(void) {   // <<<NN, 128>>>
    int node = blockIdx.x;
    int f = threadIdx.x;
    float dd = g_dis[node];
    float acc = dd * dd * g_h1[(size_t)node * HID + f];
    int j = g_rowptr[node], e = g_rowptr[node + 1];
    for (; j + 4 <= e; j += 4) {
        int2 e0 = g_edge[j],     e1 = g_edge[j + 1];
        int2 e2 = g_edge[j + 2], e3 = g_edge[j + 3];
        float h0 = g_h1[(size_t)e0.x * HID + f];
        float h1 = g_h1[(size_t)e1.x * HID + f];
        float h2 = g_h1[(size_t)e2.x * HID + f];
        float h3 = g_h1[(size_t)e3.x * HID + f];
        acc = fmaf(__int_as_float(e0.y), h0, acc);
        acc = fmaf(__int_as_float(e1.y), h1, acc);
        acc = fmaf(__int_as_float(e2.y), h2, acc);
        acc = fmaf(__int_as_float(e3.y), h3, acc);
    }
    for (; j < e; j++) {
        int2 ee = g_edge[j];
        acc = fmaf(__int_as_float(ee.y), g_h1[(size_t)ee.x * HID + f], acc);
    }
    g_agg[(size_t)node * HID + f] = acc;
}

// ================= weight pre-split (transpose + bf16 hi/lo) ==================
__global__ void k_wconv(const float* __restrict__ W2, const float* __restrict__ Wl1) {
    int i = blockIdx.x * blockDim.x + threadIdx.x;
    if (i < 256 * 128) {
        int n = i >> 7, k = i & 127;
        float v = W2[k * 256 + n];
        __nv_bfloat16 h = __float2bfloat16(v);
        g_W2T_hi[n * 128 + k] = __bfloat16_as_ushort(h);
        g_W2T_lo[n * 128 + k] =
            __bfloat16_as_ushort(__float2bfloat16(v - __bfloat162float(h)));
    } else if (i < 256 * 128 + 128 * 256) {
        int j = i - 256 * 128;
        int n = j >> 8, k = j & 255;
        float v = Wl1[k * 128 + n];
        __nv_bfloat16 h = __float2bfloat16(v);
        g_Wl1T_hi[n * 256 + k] = __bfloat16_as_ushort(h);
        g_Wl1T_lo[n * 256 + k] =
            __bfloat16_as_ushort(__float2bfloat16(v - __bfloat162float(h)));
    }
}

// ================= fused register-resident tensor-core MLP ====================
// smem (bytes):
//   [0,1024)    b2s (256 f32)
//   [1024,1536) bl1s (128 f32)
//   [1536,2048) wl2s (128 f32)
//   [2048,+17408)  W2 chunk hi : 64 rows x 68 words (stride pad, ≡4 mod 32)
//   [19456,+17408) W2 chunk lo
//   [36864,+18432) Wl1 chunk hi: 128 rows x 36 words (32 k-words + 4 pad)
//   [55296,+18432) Wl1 chunk lo
#define O_W2H  2048
#define O_W2L  (O_W2H + 17408)
#define O_L1H  (O_W2L + 17408)
#define O_L1L  (O_L1H + 18432)
#define SM_TOT (O_L1L + 18432)
#define MT2    128
#define NTILE2 ((NN + MT2 - 1) / MT2)

__device__ __forceinline__ void mma4(float* c, const uint32_t* a,
                                     uint32_t b0, uint32_t b1) {
    asm volatile(
        "mma.sync.aligned.m16n8k16.row.col.f32.bf16.bf16.f32 "
        "{%0,%1,%2,%3}, {%4,%5,%6,%7}, {%8,%9}, {%0,%1,%2,%3};"
        : "+f"(c[0]), "+f"(c[1]), "+f"(c[2]), "+f"(c[3])
        : "r"(a[0]), "r"(a[1]), "r"(a[2]), "r"(a[3]), "r"(b0), "r"(b1));
}
__device__ __forceinline__ void split2(float x, float y, uint32_t& h, uint32_t& l) {
    __nv_bfloat16 hx = __float2bfloat16(x), hy = __float2bfloat16(y);
    h = (uint32_t)__bfloat16_as_ushort(hx) | ((uint32_t)__bfloat16_as_ushort(hy) << 16);
    __nv_bfloat16 lx = __float2bfloat16(x - __bfloat162float(hx));
    __nv_bfloat16 ly = __float2bfloat16(y - __bfloat162float(hy));
    l = (uint32_t)__bfloat16_as_ushort(lx) | ((uint32_t)__bfloat16_as_ushort(ly) << 16);
}

__global__ __launch_bounds__(256) void k_mlp_tc(
        const float* __restrict__ b2,  const float* __restrict__ bl1,
        const float* __restrict__ Wl2, const float* __restrict__ bl2,
        float* __restrict__ out) {
    extern __shared__ char smem[];
    int tid = threadIdx.x, wid = tid >> 5, lane = tid & 31;
    int g = lane >> 2, tig = lane & 3;
    float* b2s  = (float*)smem;
    float* bl1s = (float*)(smem + 1024);
    float* wl2s = (float*)(smem + 1536);
    b2s[tid] = b2[tid];
    if (tid < 128) { bl1s[tid] = bl1[tid]; wl2s[tid] = Wl2[tid]; }

    int tile0 = blockIdx.x * MT2;
    int m0 = wid * 16;
    int rA = tile0 + m0 + g;
    int rB = rA + 8;
    rA = rA < NN ? rA : NN - 1;       // clamp; clamped rows never stored
    rB = rB < NN ? rB : NN - 1;
    const float* aggA = g_agg + (size_t)rA * 128;
    const float* aggB = g_agg + (size_t)rB * 128;
    const uint32_t* W2h = (const uint32_t*)(smem + O_W2H);
    const uint32_t* W2l = (const uint32_t*)(smem + O_W2L);
    const uint32_t* L1h = (const uint32_t*)(smem + O_L1H);
    const uint32_t* L1l = (const uint32_t*)(smem + O_L1L);

    float c2[64];                      // GEMM2 accumulators: 16 n-tiles x 4
    #pragma unroll
    for (int i = 0; i < 64; i++) c2[i] = 0.f;

    for (int nc = 0; nc < 4; nc++) {
        // ---- stage W2 n-chunk [nc*64..+64) x k128 and Wl1 k-chunk [nc*64..+64) x n128
        __syncthreads();
        {
            uint32_t* dW2h = (uint32_t*)(smem + O_W2H);
            uint32_t* dW2l = (uint32_t*)(smem + O_W2L);
            const uint4* sh4 = (const uint4*)g_W2T_hi;
            const uint4* sl4 = (const uint4*)g_W2T_lo;
            for (int i = tid; i < 1024; i += 256) {          // 64 rows x 16 q
                int r = i >> 4, q = i & 15;
                int srci = (nc * 64 + r) * 16 + q;
                *(uint4*)(dW2h + r * 68 + q * 4) = sh4[srci];
                *(uint4*)(dW2l + r * 68 + q * 4) = sl4[srci];
            }
            uint32_t* dL1h = (uint32_t*)(smem + O_L1H);
            uint32_t* dL1l = (uint32_t*)(smem + O_L1L);
            const uint4* lh4 = (const uint4*)g_Wl1T_hi;
            const uint4* ll4 = (const uint4*)g_Wl1T_lo;
            for (int i = tid; i < 1024; i += 256) {          // 128 rows x 8 q
                int r = i >> 3, q = i & 7;
                int srci = r * 32 + nc * 8 + q;
                *(uint4*)(dL1h + r * 36 + q * 4) = lh4[srci];
                *(uint4*)(dL1l + r * 36 + q * 4) = ll4[srci];
            }
        }
        __syncthreads();

        // ---- GEMM1 chunk: c1 = agg(K=128) @ W2[:, nc*64..+64)
        float c1[32];
        #pragma unroll
        for (int i = 0; i < 32; i++) c1[i] = 0.f;
        #pragma unroll
        for (int ks = 0; ks < 8; ks++) {
            int k0 = ks * 16 + tig * 2;
            float2 vA0 = *(const float2*)(aggA + k0);
            float2 vB0 = *(const float2*)(aggB + k0);
            float2 vA1 = *(const float2*)(aggA + k0 + 8);
            float2 vB1 = *(const float2*)(aggB + k0 + 8);
            uint32_t ah[4], al[4];
            split2(vA0.x, vA0.y, ah[0], al[0]);
            split2(vB0.x, vB0.y, ah[1], al[1]);
            split2(vA1.x, vA1.y, ah[2], al[2]);
            split2(vB1.x, vB1.y, ah[3], al[3]);
            #pragma unroll
            for (int nt = 0; nt < 8; nt++) {
                int bw = (nt * 8 + g) * 68 + ks * 8 + tig;
                uint32_t bh0 = W2h[bw], bh1 = W2h[bw + 4];
                uint32_t bl0 = W2l[bw], bl1r = W2l[bw + 4];
                mma4(c1 + nt * 4, ah, bh0, bh1);
                mma4(c1 + nt * 4, al, bh0, bh1);
                mma4(c1 + nt * 4, ah, bl0, bl1r);
            }
        }

        // ---- bias+relu+split in regs; feed directly as GEMM2 A (k-chunk nc)
        uint32_t h2h[16], h2l[16];     // per n-tile: [0]=rowg klow,[1]=rowg+8 klow order below
        #pragma unroll
        for (int nt = 0; nt < 8; nt++) {
            int col = nc * 64 + nt * 8 + tig * 2;
            float v0 = fmaxf(c1[nt * 4 + 0] + b2s[col],     0.f);
            float v1 = fmaxf(c1[nt * 4 + 1] + b2s[col + 1], 0.f);
            float v2 = fmaxf(c1[nt * 4 + 2] + b2s[col],     0.f);
            float v3 = fmaxf(c1[nt * 4 + 3] + b2s[col + 1], 0.f);
            split2(v0, v1, h2h[nt * 2],     h2l[nt * 2]);       // row g
            split2(v2, v3, h2h[nt * 2 + 1], h2l[nt * 2 + 1]);   // row g+8
        }
        // GEMM2 partial: k-local steps ks2=0..3; A tiles = c1 tiles 2ks2, 2ks2+1
        #pragma unroll
        for (int ks2 = 0; ks2 < 4; ks2++) {
            uint32_t ah[4], al[4];
            ah[0] = h2h[4 * ks2];     al[0] = h2l[4 * ks2];
            ah[1] = h2h[4 * ks2 + 1]; al[1] = h2l[4 * ks2 + 1];
            ah[2] = h2h[4 * ks2 + 2]; al[2] = h2l[4 * ks2 + 2];
            ah[3] = h2h[4 * ks2 + 3]; al[3] = h2l[4 * ks2 + 3];
            #pragma unroll
            for (int nt2 = 0; nt2 < 16; nt2++) {
                int bw = (nt2 * 8 + g) * 36 + ks2 * 8 + tig;
                uint32_t bh0 = L1h[bw], bh1 = L1h[bw + 4];
                uint32_t bl0 = L1l[bw], bl1r = L1l[bw + 4];
                mma4(c2 + nt2 * 4, ah, bh0, bh1);
                mma4(c2 + nt2 * 4, al, bh0, bh1);
                mma4(c2 + nt2 * 4, ah, bl0, bl1r);
            }
        }
    }

    // ---- GEMM3 epilogue in regs: out = relu(c2+bl1) . Wl2 + bl2, quad-reduced
    float sA = 0.f, sB = 0.f;
    #pragma unroll
    for (int nt2 = 0; nt2 < 16; nt2++) {
        int col = nt2 * 8 + tig * 2;
        float w0 = wl2s[col], w1 = wl2s[col + 1];
        float q0 = bl1s[col], q1 = bl1s[col + 1];
        sA = fmaf(fmaxf(c2[nt2 * 4 + 0] + q0, 0.f), w0, sA);
        sA = fmaf(fmaxf(c2[nt2 * 4 + 1] + q1, 0.f), w1, sA);
        sB = fmaf(fmaxf(c2[nt2 * 4 + 2] + q0, 0.f), w0, sB);
        sB = fmaf(fmaxf(c2[nt2 * 4 + 3] + q1, 0.f), w1, sB);
    }
    sA += __shfl_xor_sync(0xFFFFFFFFu, sA, 1);
    sA += __shfl_xor_sync(0xFFFFFFFFu, sA, 2);
    sB += __shfl_xor_sync(0xFFFFFFFFu, sB, 1);
    sB += __shfl_xor_sync(0xFFFFFFFFu, sB, 2);
    if (tig == 0) {
        float bl2v = bl2[0];
        int nodeA = tile0 + m0 + g;
        int nodeB = nodeA + 8;
        if (nodeA < NN) out[nodeA] = sA + bl2v;
        if (nodeB < NN) out[nodeB] = sB + bl2v;
    }
}

// ---------------- launch ------------------------------------------------------
extern "C" void kernel_launch(void* const* d_in, const int* in_sizes, int n_in,
                              void* d_out, int out_size) {
    const float* x   = (const float*)d_in[0];
    const void*  ei  = d_in[1];
    const float* w   = (const float*)d_in[2];
    const float* W1  = (const float*)d_in[3];
    const float* b1  = (const float*)d_in[4];
    const float* W2  = (const float*)d_in[5];
    const float* b2  = (const float*)d_in[6];
    const float* Wl1 = (const float*)d_in[7];
    const float* bl1 = (const float*)d_in[8];
    const float* Wl2 = (const float*)d_in[9];
    const float* bl2 = (const float*)d_in[10];
    float* out = (float*)d_out;

    const int TB = 256;
    const int EB = (NE + TB - 1) / TB;
    const int VB = (NN + TB - 1) / TB;

    static int smem_set = 0;
    if (!smem_set) {
        cudaFuncSetAttribute(k_mlp_tc, cudaFuncAttributeMaxDynamicSharedMemorySize, SM_TOT);
        smem_set = 1;
    }

    k_init    <<<VB, TB>>>();
    k_wconv   <<<256, TB>>>(W2, Wl1);
    k_conv_deg<<<EB, TB>>>(ei, w);
    k_scan1   <<<NCHUNK, SCHUNK>>>();
    k_scan2   <<<1, 1>>>();
    k_scan3   <<<VB, TB>>>();
    k_fill    <<<EB, TB>>>(w, x);
    k_expand  <<<(NN * 32 + TB - 1) / TB, TB>>>(x, W1, b1);
    k_agg     <<<NN, HID>>>();
    k_mlp_tc  <<<NTILE2, TB, SM_TOT>>>(b2, bl1, Wl2, bl2, out);
}